// round 15
// baseline (speedup 1.0000x reference)
#include <cuda_runtime.h>
#include <cuda_fp16.h>
#include <cstdint>
#include <cstddef>

#define N_BATCH 4
#define C_IN    256
#define HW      4096
#define E_DIM   128
#define OC      384   // 3*E
#define KSPLIT  8
#define VS_SCALE 256.0f
#define VS_INV   0.00390625f

#define NSTAGE  4
#define SMEM_DYN (2 * NSTAGE * 128 * 40 * (int)sizeof(__half))   // 81920 B

// ---------------- scratch (static device globals; no runtime allocation) ----------------
__device__ __half g_qkv[(size_t)N_BATCH * OC * HW];          //  12.6 MB (n,o,p) flat, fp16
__device__ __half g_S[(size_t)N_BATCH * HW * HW];            // 134.2 MB exp(scores), fp16
__device__ float  g_colpart[(size_t)N_BATCH * 32 * HW];      //   2.1 MB per-i-block column partials
__device__ __half g_VsT[(size_t)N_BATCH * E_DIM * HW];       //   4.2 MB (n,d,j) = 256*V^T/colsum, fp16
__device__ __half g_Opart[(size_t)KSPLIT * N_BATCH * HW * E_DIM]; // 33.6 MB split-K partials, fp16

// ---------------- helpers ----------------
__device__ __forceinline__ uint32_t f2tf32(float x) {
    uint32_t r;
    asm("cvt.rna.tf32.f32 %0, %1;" : "=r"(r) : "f"(x));
    return r;
}

// fast exp for |x| <~ 2 : ~1e-7 relative error, pure FMA/ALU
__device__ __forceinline__ float fexp(float x) {
    float t = x * 1.4426950408889634f;
    int   ri = __float2int_rn(t);
    float f = t - (float)ri;
    float u = f * 0.6931471805599453f;
    float p = 1.3888889e-3f;
    p = fmaf(p, u, 8.3333333e-3f);
    p = fmaf(p, u, 4.1666667e-2f);
    p = fmaf(p, u, 1.6666667e-1f);
    p = fmaf(p, u, 0.5f);
    p = fmaf(p, u, 1.0f);
    p = fmaf(p, u, 1.0f);
    return p * __int_as_float((ri + 127) << 23);
}

__device__ __forceinline__ void mma_tf32(float c[4],
                                         const uint32_t a[4],
                                         const uint32_t b[2]) {
    asm volatile(
        "mma.sync.aligned.m16n8k8.row.col.f32.tf32.tf32.f32 "
        "{%0,%1,%2,%3}, {%4,%5,%6,%7}, {%8,%9}, {%0,%1,%2,%3};"
        : "+f"(c[0]), "+f"(c[1]), "+f"(c[2]), "+f"(c[3])
        : "r"(a[0]), "r"(a[1]), "r"(a[2]), "r"(a[3]), "r"(b[0]), "r"(b[1]));
}
__device__ __forceinline__ void mma_f16(float c[4],
                                        const uint32_t a[4],
                                        const uint32_t b[2]) {
    asm volatile(
        "mma.sync.aligned.m16n8k16.row.col.f32.f16.f16.f32 "
        "{%0,%1,%2,%3}, {%4,%5,%6,%7}, {%8,%9}, {%0,%1,%2,%3};"
        : "+f"(c[0]), "+f"(c[1]), "+f"(c[2]), "+f"(c[3])
        : "r"(a[0]), "r"(a[1]), "r"(a[2]), "r"(a[3]), "r"(b[0]), "r"(b[1]));
}

// ldmatrix x4
__device__ __forceinline__ void ldsm_x4(uint32_t& r0, uint32_t& r1,
                                        uint32_t& r2, uint32_t& r3,
                                        const void* p) {
    uint32_t addr = (uint32_t)__cvta_generic_to_shared(p);
    asm volatile("ldmatrix.sync.aligned.m8n8.x4.shared.b16 {%0,%1,%2,%3}, [%4];\n"
                 : "=r"(r0), "=r"(r1), "=r"(r2), "=r"(r3) : "r"(addr));
}

// cp.async 16B helpers
__device__ __forceinline__ void cp16(void* smem_dst, const void* gsrc) {
    uint32_t s = (uint32_t)__cvta_generic_to_shared(smem_dst);
    asm volatile("cp.async.cg.shared.global [%0], [%1], 16;\n" :: "r"(s), "l"(gsrc));
}
__device__ __forceinline__ void cp_commit() {
    asm volatile("cp.async.commit_group;\n");
}
template <int N>
__device__ __forceinline__ void cp_wait() {
    asm volatile("cp.async.wait_group %0;\n" :: "n"(N));
}

// ================= async 4-stage fp16 GEMM core (ldmatrix) ================
// C[128x128] fp32 accum, A/B fp16 [row][k] global, k-tile 32.
// 256 threads = 8 warps 4(M)x2(N), warp tile 32x64.
// Steady state keeps THREE tile-loads in flight (wait_group<3>).
// k-chunk mma order identical to the 3-stage core -> bit-identical results.
__device__ __forceinline__ void gemm_async_f16(
    const __half* __restrict__ Abase, int lda,
    const __half* __restrict__ Bbase, int ldb,
    int ktiles,
    __half (*As)[128][40], __half (*Bs)[128][40],
    float c[2][8][4], int tid)
{
    const int lane = tid & 31, warp = tid >> 5;
    const int wm = warp & 3, wn = warp >> 2;
    const int r0 = tid >> 2, h8 = (tid & 3) << 3;
    const int lrow = lane & 15, lcol = (lane >> 4) << 3;

    auto issue = [&](int kt, int buf) {
        const int k0 = kt * 32;
        cp16(&As[buf][r0][h8],      Abase + (size_t)r0 * lda + k0 + h8);
        cp16(&As[buf][r0 + 64][h8], Abase + (size_t)(r0 + 64) * lda + k0 + h8);
        cp16(&Bs[buf][r0][h8],      Bbase + (size_t)r0 * ldb + k0 + h8);
        cp16(&Bs[buf][r0 + 64][h8], Bbase + (size_t)(r0 + 64) * ldb + k0 + h8);
        cp_commit();
    };

    issue(0, 0);
    issue(1, 1);
    issue(2, 2);
    for (int kt = 0; kt < ktiles; kt++) {
        const int buf = kt % NSTAGE;
        if (kt + 3 < ktiles)        { issue(kt + 3, (kt + 3) % NSTAGE); cp_wait<3>(); }
        else if (kt + 3 == ktiles)  { cp_wait<2>(); }
        else if (kt + 2 == ktiles)  { cp_wait<1>(); }
        else                        { cp_wait<0>(); }
        __syncthreads();

#pragma unroll
        for (int kk = 0; kk < 2; kk++) {
            const int kb = kk << 4;
            uint32_t a[2][4];
#pragma unroll
            for (int ms = 0; ms < 2; ms++) {
                int rb = wm * 32 + ms * 16;
                ldsm_x4(a[ms][0], a[ms][1], a[ms][2], a[ms][3],
                        &As[buf][rb + lrow][kb + lcol]);
            }
            uint32_t b[8][2];
#pragma unroll
            for (int g = 0; g < 4; g++) {
                int nb = wn * 64 + g * 16;
                uint32_t m0, m1, m2, m3;
                ldsm_x4(m0, m1, m2, m3, &Bs[buf][nb + lrow][kb + lcol]);
                b[2 * g][0]     = m0; b[2 * g][1]     = m2;
                b[2 * g + 1][0] = m1; b[2 * g + 1][1] = m3;
            }
#pragma unroll
            for (int ms = 0; ms < 2; ms++)
#pragma unroll
                for (int ns = 0; ns < 8; ns++)
                    mma_f16(c[ms][ns], a[ms], b[ns]);
        }
        __syncthreads();
    }
}

// ================= LDG+cvt tf32 GEMM core (external fp32 inputs) ==========
template <bool B_KN>
__device__ __forceinline__ void gemm_main(
    const float* __restrict__ Abase, int lda,
    const float* __restrict__ Bbase, int ldb,
    int ktiles,
    uint32_t (*As)[20], uint32_t (*Bs)[20],
    float c[2][8][4], int tid)
{
    const int lane = tid & 31, warp = tid >> 5;
    const int gid = lane >> 2, tig = lane & 3;
    const int wm = warp & 3, wn = warp >> 2;

    for (int kt = 0; kt < ktiles; kt++) {
        const int k0 = kt * 16;
#pragma unroll
        for (int i = 0; i < 2; i++) {
            int t = tid + 256 * i;
            int row = t >> 2, c4 = (t & 3) << 2;
            float4 v = __ldg(reinterpret_cast<const float4*>(
                Abase + (size_t)row * lda + k0 + c4));
            As[row][c4 + 0] = f2tf32(v.x);
            As[row][c4 + 1] = f2tf32(v.y);
            As[row][c4 + 2] = f2tf32(v.z);
            As[row][c4 + 3] = f2tf32(v.w);
        }
        if (B_KN) {
#pragma unroll
            for (int i = 0; i < 2; i++) {
                int t = tid + 256 * i;
                int k = t >> 5, c4 = (t & 31) << 2;
                float4 v = __ldg(reinterpret_cast<const float4*>(
                    Bbase + (size_t)(k0 + k) * ldb + c4));
                Bs[c4 + 0][k] = f2tf32(v.x);
                Bs[c4 + 1][k] = f2tf32(v.y);
                Bs[c4 + 2][k] = f2tf32(v.z);
                Bs[c4 + 3][k] = f2tf32(v.w);
            }
        } else {
#pragma unroll
            for (int i = 0; i < 2; i++) {
                int t = tid + 256 * i;
                int row = t >> 2, c4 = (t & 3) << 2;
                float4 v = __ldg(reinterpret_cast<const float4*>(
                    Bbase + (size_t)row * ldb + k0 + c4));
                Bs[row][c4 + 0] = f2tf32(v.x);
                Bs[row][c4 + 1] = f2tf32(v.y);
                Bs[row][c4 + 2] = f2tf32(v.z);
                Bs[row][c4 + 3] = f2tf32(v.w);
            }
        }
        __syncthreads();

#pragma unroll
        for (int kk = 0; kk < 2; kk++) {
            const int kb = kk << 3;
            uint32_t a[2][4];
#pragma unroll
            for (int ms = 0; ms < 2; ms++) {
                int rb = wm * 32 + ms * 16;
                a[ms][0] = As[rb + gid][kb + tig];
                a[ms][1] = As[rb + gid + 8][kb + tig];
                a[ms][2] = As[rb + gid][kb + tig + 4];
                a[ms][3] = As[rb + gid + 8][kb + tig + 4];
            }
            uint32_t b[8][2];
#pragma unroll
            for (int ns = 0; ns < 8; ns++) {
                int nb = wn * 64 + ns * 8;
                b[ns][0] = Bs[nb + gid][kb + tig];
                b[ns][1] = Bs[nb + gid][kb + tig + 4];
            }
#pragma unroll
            for (int ms = 0; ms < 2; ms++)
#pragma unroll
                for (int ns = 0; ns < 8; ns++)
                    mma_tf32(c[ms][ns], a[ms], b[ns]);
        }
        __syncthreads();
    }
}

// ---------------- K1: QKV projection (stores fp16) ------------------------
__global__ void __launch_bounds__(256, 2) k_qkv(
    const float* __restrict__ x, const float* __restrict__ Wqkv,
    const float* __restrict__ bqkv)
{
    __shared__ uint32_t As[128][20];
    __shared__ uint32_t Bs[128][20];
    const int n = blockIdx.z;
    const int m0 = blockIdx.y * 128;
    const int p0 = blockIdx.x * 128;
    const float* Abase = Wqkv + (size_t)m0 * C_IN;               // [M][K]
    const float* Bbase = x + (size_t)n * C_IN * HW + p0;         // [K][N]
    float c[2][8][4] = {};
    gemm_main<true>(Abase, C_IN, Bbase, HW, C_IN / 16, As, Bs, c, threadIdx.x);

    const int lane = threadIdx.x & 31, warp = threadIdx.x >> 5;
    const int gid = lane >> 2, tig = lane & 3, wm = warp & 3, wn = warp >> 2;
    __half* Cb = g_qkv + (size_t)n * OC * HW;
#pragma unroll
    for (int ms = 0; ms < 2; ms++) {
        const int r0 = m0 + wm * 32 + ms * 16 + gid;
        const float b0 = bqkv[r0], b1 = bqkv[r0 + 8];
#pragma unroll
        for (int ns = 0; ns < 8; ns++) {
            const int col = p0 + wn * 64 + ns * 8 + 2 * tig;
            *(__half2*)(Cb + (size_t)r0 * HW + col) =
                __halves2half2(__float2half_rn(c[ms][ns][0] + b0),
                               __float2half_rn(c[ms][ns][1] + b0));
            *(__half2*)(Cb + (size_t)(r0 + 8) * HW + col) =
                __halves2half2(__float2half_rn(c[ms][ns][2] + b1),
                               __float2half_rn(c[ms][ns][3] + b1));
        }
    }
}

// ---------------- K2: S' = fp16(exp(Q K^T / 64)) + column partials --------
// Epilogue stages the 128x128 fp16 tile through smem -> 16B coalesced STG.
__global__ void __launch_bounds__(256, 2) k_scores()
{
    extern __shared__ __align__(16) __half dynsm[];
    __half (*As)[128][40] = reinterpret_cast<__half (*)[128][40]>(dynsm);
    __half (*Bs)[128][40] = reinterpret_cast<__half (*)[128][40]>(dynsm + NSTAGE * 128 * 40);

    const int n = blockIdx.z;
    const int i0 = blockIdx.y * 128;
    const int j0 = blockIdx.x * 128;
    const __half* qb = g_qkv + (size_t)n * OC * HW;
    float c[2][8][4] = {};
    gemm_async_f16(qb + (size_t)i0 * 384, 384, qb + (size_t)j0 * 384 + 128, 384,
                   128 / 32, As, Bs, c, threadIdx.x);

    const int tid = threadIdx.x;
    const int lane = tid & 31, warp = tid >> 5;
    const int gid = lane >> 2, tig = lane & 3, wm = warp & 3, wn = warp >> 2;
    const float scale = 0.015625f;  // 1/sqrt(4096)

    __half2* sm = reinterpret_cast<__half2*>(dynsm);          // [128][68] staging
    float* part = reinterpret_cast<float*>(sm + 128 * 68);

    float csum[8][2];
#pragma unroll
    for (int ns = 0; ns < 8; ns++) { csum[ns][0] = 0.f; csum[ns][1] = 0.f; }

#pragma unroll
    for (int ms = 0; ms < 2; ms++) {
        const int row = wm * 32 + ms * 16 + gid;
#pragma unroll
        for (int ns = 0; ns < 8; ns++) {
            const int ch2 = wn * 32 + ns * 4 + tig;
            // round exp to fp16 HERE; colsum adds the ROUNDED values so the
            // normalization matches the stored matrix exactly.
            __half h0 = __float2half_rn(fexp(c[ms][ns][0] * scale));
            __half h1 = __float2half_rn(fexp(c[ms][ns][1] * scale));
            __half h2 = __float2half_rn(fexp(c[ms][ns][2] * scale));
            __half h3 = __float2half_rn(fexp(c[ms][ns][3] * scale));
            sm[row * 68 + ch2]       = __halves2half2(h0, h1);
            sm[(row + 8) * 68 + ch2] = __halves2half2(h2, h3);
            csum[ns][0] += __half2float(h0) + __half2float(h2);
            csum[ns][1] += __half2float(h1) + __half2float(h3);
        }
    }
#pragma unroll
    for (int ns = 0; ns < 8; ns++)
#pragma unroll
        for (int jj = 0; jj < 2; jj++) {
            float v = csum[ns][jj];
            v += __shfl_xor_sync(0xffffffffu, v, 4);
            v += __shfl_xor_sync(0xffffffffu, v, 8);
            v += __shfl_xor_sync(0xffffffffu, v, 16);
            if (gid == 0)
                part[wm * 128 + wn * 64 + ns * 8 + 2 * tig + jj] = v;
        }
    __syncthreads();

    __half* Sb = g_S + (size_t)n * HW * HW;
#pragma unroll
    for (int it = 0; it < 8; it++) {
        int q = it * 256 + tid;
        int row = q >> 4, ch = q & 15;
        float4 v = *reinterpret_cast<const float4*>(sm + row * 68 + ch * 4);
        *reinterpret_cast<float4*>(Sb + (size_t)(i0 + row) * HW + j0 + ch * 8) = v;
    }
    if (tid < 128) {
        float s = part[tid] + part[128 + tid] + part[256 + tid] + part[384 + tid];
        g_colpart[((size_t)n * 32 + blockIdx.y) * HW + j0 + tid] = s;
    }
}

// ---------------- K3: colsum reduce + VsT[d][j] = fp16(256*V[j,d]/colsum[j])
__global__ void k_vscale()
{
    __shared__ float ps[32][33];
    __shared__ float t[32][33];
    const int n = blockIdx.y;
    const int j0 = blockIdx.x * 32;
    const int tx = threadIdx.x, ty = threadIdx.y;

    ps[ty][tx] = g_colpart[((size_t)n * 32 + ty) * HW + j0 + tx];
    __syncthreads();
#pragma unroll
    for (int s = 16; s > 0; s >>= 1) {
        if (ty < s) ps[ty][tx] += ps[ty + s][tx];
        __syncthreads();
    }
    const float inv = VS_SCALE / ps[0][tx];

    const __half* qb = g_qkv + (size_t)n * OC * HW;
    __half* Vb = g_VsT + (size_t)n * E_DIM * HW;
#pragma unroll
    for (int dd = 0; dd < 4; dd++) {
        t[ty][tx] = __half2float(qb[(size_t)(j0 + ty) * 384 + 256 + dd * 32 + tx]);
        __syncthreads();
        Vb[(size_t)(dd * 32 + ty) * HW + j0 + tx] = __float2half_rn(t[tx][ty] * inv);
        __syncthreads();
    }
}

// ---------------- K4: O_partial = S' @ VsT^T (fp16 MMA, split-K x8) -------
__global__ void __launch_bounds__(256, 2) k_pv()
{
    extern __shared__ __align__(16) __half dynsm[];
    __half (*As)[128][40] = reinterpret_cast<__half (*)[128][40]>(dynsm);
    __half (*Bs)[128][40] = reinterpret_cast<__half (*)[128][40]>(dynsm + NSTAGE * 128 * 40);

    const int n = blockIdx.z;
    const int i0 = blockIdx.y * 128;
    const int split = blockIdx.x;
    const int jbase = split * (HW / KSPLIT);
    const __half* Abase = g_S + (size_t)n * HW * HW + (size_t)i0 * HW + jbase;
    const __half* Bbase = g_VsT + (size_t)n * E_DIM * HW + jbase;
    float c[2][8][4] = {};
    gemm_async_f16(Abase, HW, Bbase, HW, (HW / KSPLIT) / 32, As, Bs, c, threadIdx.x);

    const int lane = threadIdx.x & 31, warp = threadIdx.x >> 5;
    const int gid = lane >> 2, tig = lane & 3, wm = warp & 3, wn = warp >> 2;
    __half* Ob = g_Opart + ((size_t)split * N_BATCH + n) * HW * E_DIM;
#pragma unroll
    for (int ms = 0; ms < 2; ms++) {
        const int r0 = i0 + wm * 32 + ms * 16 + gid;
#pragma unroll
        for (int ns = 0; ns < 8; ns++) {
            const int col = wn * 64 + ns * 8 + 2 * tig;
            *(__half2*)(Ob + (size_t)r0 * E_DIM + col) =
                __halves2half2(__float2half_rn(c[ms][ns][0] * VS_INV),
                               __float2half_rn(c[ms][ns][1] * VS_INV));
            *(__half2*)(Ob + (size_t)(r0 + 8) * E_DIM + col) =
                __halves2half2(__float2half_rn(c[ms][ns][2] * VS_INV),
                               __float2half_rn(c[ms][ns][3] * VS_INV));
        }
    }
}

// ---------------- K5: output projection + split-K reduce ------------------
__global__ void __launch_bounds__(256, 2) k_proj(
    float* __restrict__ out, const float* __restrict__ Wout,
    const float* __restrict__ bout)
{
    __shared__ uint32_t As[128][20];
    __shared__ uint32_t Bs[128][20];
    const int n = blockIdx.z;
    const int c0 = blockIdx.y * 128;
    const int p0 = blockIdx.x * 128;
    const int tid = threadIdx.x;
    const float* Abase = Wout + (size_t)c0 * E_DIM;
    const __half* Bp0 = g_Opart + (size_t)n * HW * E_DIM + p0;
    const size_t sstr = (size_t)N_BATCH * HW * E_DIM;

    const int lane = tid & 31, warp = tid >> 5;
    const int gid = lane >> 2, tig = lane & 3;
    const int wm = warp & 3, wn = warp >> 2;
    float c[2][8][4] = {};

    for (int kt = 0; kt < E_DIM / 16; kt++) {
        const int k0 = kt * 16;
#pragma unroll
        for (int i = 0; i < 2; i++) {
            int t = tid + 256 * i;
            int row = t >> 2, c4 = (t & 3) << 2;
            float4 v = __ldg(reinterpret_cast<const float4*>(
                Abase + (size_t)row * E_DIM + k0 + c4));
            As[row][c4 + 0] = f2tf32(v.x);
            As[row][c4 + 1] = f2tf32(v.y);
            As[row][c4 + 2] = f2tf32(v.z);
            As[row][c4 + 3] = f2tf32(v.w);
        }
#pragma unroll
        for (int i = 0; i < 2; i++) {
            int t = tid + 256 * i;
            int k = t >> 5, c4 = (t & 31) << 2;
            size_t off = (size_t)(k0 + k) * HW + c4;
            float s0 = 0.f, s1 = 0.f, s2 = 0.f, s3 = 0.f;
#pragma unroll
            for (int s = 0; s < KSPLIT; s++) {
                const __half* bp = Bp0 + s * sstr + off;
                __half2 p01 = *(const __half2*)(bp);
                __half2 p23 = *(const __half2*)(bp + 2);
                s0 += __half2float(p01.x); s1 += __half2float(p01.y);
                s2 += __half2float(p23.x); s3 += __half2float(p23.y);
            }
            Bs[c4 + 0][k] = f2tf32(s0);
            Bs[c4 + 1][k] = f2tf32(s1);
            Bs[c4 + 2][k] = f2tf32(s2);
            Bs[c4 + 3][k] = f2tf32(s3);
        }
        __syncthreads();

#pragma unroll
        for (int kk = 0; kk < 2; kk++) {
            const int kb = kk << 3;
            uint32_t a[2][4];
#pragma unroll
            for (int ms = 0; ms < 2; ms++) {
                int rb = wm * 32 + ms * 16;
                a[ms][0] = As[rb + gid][kb + tig];
                a[ms][1] = As[rb + gid + 8][kb + tig];
                a[ms][2] = As[rb + gid][kb + tig + 4];
                a[ms][3] = As[rb + gid + 8][kb + tig + 4];
            }
            uint32_t b[8][2];
#pragma unroll
            for (int ns = 0; ns < 8; ns++) {
                int nb = wn * 64 + ns * 8;
                b[ns][0] = Bs[nb + gid][kb + tig];
                b[ns][1] = Bs[nb + gid][kb + tig + 4];
            }
#pragma unroll
            for (int ms = 0; ms < 2; ms++)
#pragma unroll
                for (int ns = 0; ns < 8; ns++)
                    mma_tf32(c[ms][ns], a[ms], b[ns]);
        }
        __syncthreads();
    }

    float* Yb = out + (size_t)n * C_IN * HW;
#pragma unroll
    for (int ms = 0; ms < 2; ms++) {
        const int r0 = c0 + wm * 32 + ms * 16 + gid;
        const float b0 = bout[r0], b1 = bout[r0 + 8];
#pragma unroll
        for (int ns = 0; ns < 8; ns++) {
            const int col = p0 + wn * 64 + ns * 8 + 2 * tig;
            *(float2*)(Yb + (size_t)r0 * HW + col) =
                make_float2(c[ms][ns][0] + b0, c[ms][ns][1] + b0);
            *(float2*)(Yb + (size_t)(r0 + 8) * HW + col) =
                make_float2(c[ms][ns][2] + b1, c[ms][ns][3] + b1);
        }
    }
}

// ---------------- launch ---------------------------------------------------
extern "C" void kernel_launch(void* const* d_in, const int* in_sizes, int n_in,
                              void* d_out, int out_size)
{
    (void)in_sizes; (void)n_in; (void)out_size;
    const float* x    = (const float*)d_in[0];
    const float* Wqkv = (const float*)d_in[1];
    const float* bqkv = (const float*)d_in[2];
    const float* Wout = (const float*)d_in[3];
    const float* bout = (const float*)d_in[4];
    float* out = (float*)d_out;

    // attribute sets (not allocations); applied before the pre-capture call
    cudaFuncSetAttribute(k_scores, cudaFuncAttributeMaxDynamicSharedMemorySize, SMEM_DYN);
    cudaFuncSetAttribute(k_pv,     cudaFuncAttributeMaxDynamicSharedMemorySize, SMEM_DYN);

    dim3 blk(256);
    k_qkv<<<dim3(HW / 128, OC / 128, N_BATCH), blk>>>(x, Wqkv, bqkv);
    k_scores<<<dim3(HW / 128, HW / 128, N_BATCH), blk, SMEM_DYN>>>();
    k_vscale<<<dim3(HW / 32, N_BATCH), dim3(32, 32)>>>();
    k_pv<<<dim3(KSPLIT, HW / 128, N_BATCH), blk, SMEM_DYN>>>();
    k_proj<<<dim3(HW / 128, C_IN / 128, N_BATCH), blk>>>(out, Wout, bout);
}

// round 16
// speedup vs baseline: 1.0227x; 1.0227x over previous
#include <cuda_runtime.h>
#include <cuda_fp16.h>
#include <cstdint>
#include <cstddef>

#define N_BATCH 4
#define C_IN    256
#define HW      4096
#define E_DIM   128
#define OC      384   // 3*E
#define KSPLIT  8
#define VS_SCALE 256.0f
#define VS_INV   0.00390625f

#define NSTAGE  3
#define SMEM_DYN (2 * NSTAGE * 128 * 40 * (int)sizeof(__half))   // 61440 B
#define TILE_ELEMS (128 * 128)

// ---------------- scratch (static device globals; no runtime allocation) ----------------
__device__ __half g_qkv[(size_t)N_BATCH * OC * HW];          //  12.6 MB (n,o,p) flat, fp16
// S stored TILED: tile (n, ib, jb) contiguous 128x128 row-major (32 KB)
__device__ __half g_S[(size_t)N_BATCH * 32 * 32 * TILE_ELEMS];    // 134.2 MB
__device__ float  g_colpart[(size_t)N_BATCH * 32 * HW];      //   2.1 MB per-i-block column partials
__device__ __half g_VsT[(size_t)N_BATCH * E_DIM * HW];       //   4.2 MB (n,d,j) = 256*V^T/colsum, fp16
__device__ __half g_Opart[(size_t)KSPLIT * N_BATCH * HW * E_DIM]; // 33.6 MB split-K partials, fp16

// ---------------- helpers ----------------
__device__ __forceinline__ uint32_t f2tf32(float x) {
    uint32_t r;
    asm("cvt.rna.tf32.f32 %0, %1;" : "=r"(r) : "f"(x));
    return r;
}

// fast exp for |x| <~ 2 : ~1e-7 relative error, pure FMA/ALU
__device__ __forceinline__ float fexp(float x) {
    float t = x * 1.4426950408889634f;
    int   ri = __float2int_rn(t);
    float f = t - (float)ri;
    float u = f * 0.6931471805599453f;
    float p = 1.3888889e-3f;
    p = fmaf(p, u, 8.3333333e-3f);
    p = fmaf(p, u, 4.1666667e-2f);
    p = fmaf(p, u, 1.6666667e-1f);
    p = fmaf(p, u, 0.5f);
    p = fmaf(p, u, 1.0f);
    p = fmaf(p, u, 1.0f);
    return p * __int_as_float((ri + 127) << 23);
}

__device__ __forceinline__ void mma_tf32(float c[4],
                                         const uint32_t a[4],
                                         const uint32_t b[2]) {
    asm volatile(
        "mma.sync.aligned.m16n8k8.row.col.f32.tf32.tf32.f32 "
        "{%0,%1,%2,%3}, {%4,%5,%6,%7}, {%8,%9}, {%0,%1,%2,%3};"
        : "+f"(c[0]), "+f"(c[1]), "+f"(c[2]), "+f"(c[3])
        : "r"(a[0]), "r"(a[1]), "r"(a[2]), "r"(a[3]), "r"(b[0]), "r"(b[1]));
}
__device__ __forceinline__ void mma_f16(float c[4],
                                        const uint32_t a[4],
                                        const uint32_t b[2]) {
    asm volatile(
        "mma.sync.aligned.m16n8k16.row.col.f32.f16.f16.f32 "
        "{%0,%1,%2,%3}, {%4,%5,%6,%7}, {%8,%9}, {%0,%1,%2,%3};"
        : "+f"(c[0]), "+f"(c[1]), "+f"(c[2]), "+f"(c[3])
        : "r"(a[0]), "r"(a[1]), "r"(a[2]), "r"(a[3]), "r"(b[0]), "r"(b[1]));
}

// ldmatrix x4
__device__ __forceinline__ void ldsm_x4(uint32_t& r0, uint32_t& r1,
                                        uint32_t& r2, uint32_t& r3,
                                        const void* p) {
    uint32_t addr = (uint32_t)__cvta_generic_to_shared(p);
    asm volatile("ldmatrix.sync.aligned.m8n8.x4.shared.b16 {%0,%1,%2,%3}, [%4];\n"
                 : "=r"(r0), "=r"(r1), "=r"(r2), "=r"(r3) : "r"(addr));
}

// cp.async 16B helpers
__device__ __forceinline__ void cp16(void* smem_dst, const void* gsrc) {
    uint32_t s = (uint32_t)__cvta_generic_to_shared(smem_dst);
    asm volatile("cp.async.cg.shared.global [%0], [%1], 16;\n" :: "r"(s), "l"(gsrc));
}
__device__ __forceinline__ void cp_commit() {
    asm volatile("cp.async.commit_group;\n");
}
template <int N>
__device__ __forceinline__ void cp_wait() {
    asm volatile("cp.async.wait_group %0;\n" :: "n"(N));
}

// ================= async 3-stage fp16 GEMM core (ldmatrix) ================
// C[128x128] fp32 accum, A/B fp16 [row][k] global, k-tile 32. (k_scores)
__device__ __forceinline__ void gemm_async_f16(
    const __half* __restrict__ Abase, int lda,
    const __half* __restrict__ Bbase, int ldb,
    int ktiles,
    __half (*As)[128][40], __half (*Bs)[128][40],
    float c[2][8][4], int tid)
{
    const int lane = tid & 31, warp = tid >> 5;
    const int wm = warp & 3, wn = warp >> 2;
    const int r0 = tid >> 2, h8 = (tid & 3) << 3;
    const int lrow = lane & 15, lcol = (lane >> 4) << 3;

    auto issue = [&](int kt, int buf) {
        const int k0 = kt * 32;
        cp16(&As[buf][r0][h8],      Abase + (size_t)r0 * lda + k0 + h8);
        cp16(&As[buf][r0 + 64][h8], Abase + (size_t)(r0 + 64) * lda + k0 + h8);
        cp16(&Bs[buf][r0][h8],      Bbase + (size_t)r0 * ldb + k0 + h8);
        cp16(&Bs[buf][r0 + 64][h8], Bbase + (size_t)(r0 + 64) * ldb + k0 + h8);
        cp_commit();
    };

    issue(0, 0);
    issue(1, 1);
    for (int kt = 0; kt < ktiles; kt++) {
        const int buf = kt % NSTAGE;
        if (kt + 2 < ktiles)        { issue(kt + 2, (kt + 2) % NSTAGE); cp_wait<2>(); }
        else if (kt + 2 == ktiles)  { cp_wait<1>(); }
        else                        { cp_wait<0>(); }
        __syncthreads();

#pragma unroll
        for (int kk = 0; kk < 2; kk++) {
            const int kb = kk << 4;
            uint32_t a[2][4];
#pragma unroll
            for (int ms = 0; ms < 2; ms++) {
                int rb = wm * 32 + ms * 16;
                ldsm_x4(a[ms][0], a[ms][1], a[ms][2], a[ms][3],
                        &As[buf][rb + lrow][kb + lcol]);
            }
            uint32_t b[8][2];
#pragma unroll
            for (int g = 0; g < 4; g++) {
                int nb = wn * 64 + g * 16;
                uint32_t m0, m1, m2, m3;
                ldsm_x4(m0, m1, m2, m3, &Bs[buf][nb + lrow][kb + lcol]);
                b[2 * g][0]     = m0; b[2 * g][1]     = m2;
                b[2 * g + 1][0] = m1; b[2 * g + 1][1] = m3;
            }
#pragma unroll
            for (int ms = 0; ms < 2; ms++)
#pragma unroll
                for (int ns = 0; ns < 8; ns++)
                    mma_f16(c[ms][ns], a[ms], b[ns]);
        }
        __syncthreads();
    }
}

// ================= LDG+cvt tf32 GEMM core (external fp32 inputs) ==========
template <bool B_KN>
__device__ __forceinline__ void gemm_main(
    const float* __restrict__ Abase, int lda,
    const float* __restrict__ Bbase, int ldb,
    int ktiles,
    uint32_t (*As)[20], uint32_t (*Bs)[20],
    float c[2][8][4], int tid)
{
    const int lane = tid & 31, warp = tid >> 5;
    const int gid = lane >> 2, tig = lane & 3;
    const int wm = warp & 3, wn = warp >> 2;

    for (int kt = 0; kt < ktiles; kt++) {
        const int k0 = kt * 16;
#pragma unroll
        for (int i = 0; i < 2; i++) {
            int t = tid + 256 * i;
            int row = t >> 2, c4 = (t & 3) << 2;
            float4 v = __ldg(reinterpret_cast<const float4*>(
                Abase + (size_t)row * lda + k0 + c4));
            As[row][c4 + 0] = f2tf32(v.x);
            As[row][c4 + 1] = f2tf32(v.y);
            As[row][c4 + 2] = f2tf32(v.z);
            As[row][c4 + 3] = f2tf32(v.w);
        }
        if (B_KN) {
#pragma unroll
            for (int i = 0; i < 2; i++) {
                int t = tid + 256 * i;
                int k = t >> 5, c4 = (t & 31) << 2;
                float4 v = __ldg(reinterpret_cast<const float4*>(
                    Bbase + (size_t)(k0 + k) * ldb + c4));
                Bs[c4 + 0][k] = f2tf32(v.x);
                Bs[c4 + 1][k] = f2tf32(v.y);
                Bs[c4 + 2][k] = f2tf32(v.z);
                Bs[c4 + 3][k] = f2tf32(v.w);
            }
        } else {
#pragma unroll
            for (int i = 0; i < 2; i++) {
                int t = tid + 256 * i;
                int row = t >> 2, c4 = (t & 3) << 2;
                float4 v = __ldg(reinterpret_cast<const float4*>(
                    Bbase + (size_t)row * ldb + k0 + c4));
                Bs[row][c4 + 0] = f2tf32(v.x);
                Bs[row][c4 + 1] = f2tf32(v.y);
                Bs[row][c4 + 2] = f2tf32(v.z);
                Bs[row][c4 + 3] = f2tf32(v.w);
            }
        }
        __syncthreads();

#pragma unroll
        for (int kk = 0; kk < 2; kk++) {
            const int kb = kk << 3;
            uint32_t a[2][4];
#pragma unroll
            for (int ms = 0; ms < 2; ms++) {
                int rb = wm * 32 + ms * 16;
                a[ms][0] = As[rb + gid][kb + tig];
                a[ms][1] = As[rb + gid + 8][kb + tig];
                a[ms][2] = As[rb + gid][kb + tig + 4];
                a[ms][3] = As[rb + gid + 8][kb + tig + 4];
            }
            uint32_t b[8][2];
#pragma unroll
            for (int ns = 0; ns < 8; ns++) {
                int nb = wn * 64 + ns * 8;
                b[ns][0] = Bs[nb + gid][kb + tig];
                b[ns][1] = Bs[nb + gid][kb + tig + 4];
            }
#pragma unroll
            for (int ms = 0; ms < 2; ms++)
#pragma unroll
                for (int ns = 0; ns < 8; ns++)
                    mma_tf32(c[ms][ns], a[ms], b[ns]);
        }
        __syncthreads();
    }
}

// ---------------- K1: QKV projection (stores fp16) ------------------------
__global__ void __launch_bounds__(256, 2) k_qkv(
    const float* __restrict__ x, const float* __restrict__ Wqkv,
    const float* __restrict__ bqkv)
{
    __shared__ uint32_t As[128][20];
    __shared__ uint32_t Bs[128][20];
    const int n = blockIdx.z;
    const int m0 = blockIdx.y * 128;
    const int p0 = blockIdx.x * 128;
    const float* Abase = Wqkv + (size_t)m0 * C_IN;               // [M][K]
    const float* Bbase = x + (size_t)n * C_IN * HW + p0;         // [K][N]
    float c[2][8][4] = {};
    gemm_main<true>(Abase, C_IN, Bbase, HW, C_IN / 16, As, Bs, c, threadIdx.x);

    const int lane = threadIdx.x & 31, warp = threadIdx.x >> 5;
    const int gid = lane >> 2, tig = lane & 3, wm = warp & 3, wn = warp >> 2;
    __half* Cb = g_qkv + (size_t)n * OC * HW;
#pragma unroll
    for (int ms = 0; ms < 2; ms++) {
        const int r0 = m0 + wm * 32 + ms * 16 + gid;
        const float b0 = bqkv[r0], b1 = bqkv[r0 + 8];
#pragma unroll
        for (int ns = 0; ns < 8; ns++) {
            const int col = p0 + wn * 64 + ns * 8 + 2 * tig;
            *(__half2*)(Cb + (size_t)r0 * HW + col) =
                __halves2half2(__float2half_rn(c[ms][ns][0] + b0),
                               __float2half_rn(c[ms][ns][1] + b0));
            *(__half2*)(Cb + (size_t)(r0 + 8) * HW + col) =
                __halves2half2(__float2half_rn(c[ms][ns][2] + b1),
                               __float2half_rn(c[ms][ns][3] + b1));
        }
    }
}

// ---------------- K2: S' = fp16(exp(Q K^T / 64)) + column partials --------
// Stores S into CONTIGUOUS 128x128 tiles (sequential 32 KB per CTA).
__global__ void __launch_bounds__(256, 2) k_scores()
{
    extern __shared__ __align__(16) __half dynsm[];
    __half (*As)[128][40] = reinterpret_cast<__half (*)[128][40]>(dynsm);
    __half (*Bs)[128][40] = reinterpret_cast<__half (*)[128][40]>(dynsm + NSTAGE * 128 * 40);

    const int n = blockIdx.z;
    const int ib = blockIdx.y;               // i-block
    const int jb = blockIdx.x;               // j-block
    const int i0 = ib * 128, j0 = jb * 128;
    const __half* qb = g_qkv + (size_t)n * OC * HW;
    float c[2][8][4] = {};
    gemm_async_f16(qb + (size_t)i0 * 384, 384, qb + (size_t)j0 * 384 + 128, 384,
                   128 / 32, As, Bs, c, threadIdx.x);

    const int tid = threadIdx.x;
    const int lane = tid & 31, warp = tid >> 5;
    const int gid = lane >> 2, tig = lane & 3, wm = warp & 3, wn = warp >> 2;
    const float scale = 0.015625f;  // 1/sqrt(4096)

    __half2* sm = reinterpret_cast<__half2*>(dynsm);          // [128][68] staging
    float* part = reinterpret_cast<float*>(sm + 128 * 68);

    float csum[8][2];
#pragma unroll
    for (int ns = 0; ns < 8; ns++) { csum[ns][0] = 0.f; csum[ns][1] = 0.f; }

#pragma unroll
    for (int ms = 0; ms < 2; ms++) {
        const int row = wm * 32 + ms * 16 + gid;
#pragma unroll
        for (int ns = 0; ns < 8; ns++) {
            const int ch2 = wn * 32 + ns * 4 + tig;
            // round exp to fp16 HERE; colsum adds the ROUNDED values so the
            // normalization matches the stored matrix exactly.
            __half h0 = __float2half_rn(fexp(c[ms][ns][0] * scale));
            __half h1 = __float2half_rn(fexp(c[ms][ns][1] * scale));
            __half h2 = __float2half_rn(fexp(c[ms][ns][2] * scale));
            __half h3 = __float2half_rn(fexp(c[ms][ns][3] * scale));
            sm[row * 68 + ch2]       = __halves2half2(h0, h1);
            sm[(row + 8) * 68 + ch2] = __halves2half2(h2, h3);
            csum[ns][0] += __half2float(h0) + __half2float(h2);
            csum[ns][1] += __half2float(h1) + __half2float(h3);
        }
    }
#pragma unroll
    for (int ns = 0; ns < 8; ns++)
#pragma unroll
        for (int jj = 0; jj < 2; jj++) {
            float v = csum[ns][jj];
            v += __shfl_xor_sync(0xffffffffu, v, 4);
            v += __shfl_xor_sync(0xffffffffu, v, 8);
            v += __shfl_xor_sync(0xffffffffu, v, 16);
            if (gid == 0)
                part[wm * 128 + wn * 64 + ns * 8 + 2 * tig + jj] = v;
        }
    __syncthreads();

    // sequential 32 KB tile store (4 KB contiguous per iteration)
    __half* Tb = g_S + ((size_t)(n * 32 + ib) * 32 + jb) * TILE_ELEMS;
#pragma unroll
    for (int it = 0; it < 8; it++) {
        int q = it * 256 + tid;
        int row = q >> 4, ch = q & 15;
        float4 v = *reinterpret_cast<const float4*>(sm + row * 68 + ch * 4);
        *reinterpret_cast<float4*>(Tb + (size_t)row * 128 + ch * 8) = v;
    }
    if (tid < 128) {
        float s = part[tid] + part[128 + tid] + part[256 + tid] + part[384 + tid];
        g_colpart[((size_t)n * 32 + ib) * HW + j0 + tid] = s;
    }
}

// ---------------- K3: colsum reduce + VsT[d][j] = fp16(256*V[j,d]/colsum[j])
__global__ void k_vscale()
{
    __shared__ float ps[32][33];
    __shared__ float t[32][33];
    const int n = blockIdx.y;
    const int j0 = blockIdx.x * 32;
    const int tx = threadIdx.x, ty = threadIdx.y;

    ps[ty][tx] = g_colpart[((size_t)n * 32 + ty) * HW + j0 + tx];
    __syncthreads();
#pragma unroll
    for (int s = 16; s > 0; s >>= 1) {
        if (ty < s) ps[ty][tx] += ps[ty + s][tx];
        __syncthreads();
    }
    const float inv = VS_SCALE / ps[0][tx];

    const __half* qb = g_qkv + (size_t)n * OC * HW;
    __half* Vb = g_VsT + (size_t)n * E_DIM * HW;
#pragma unroll
    for (int dd = 0; dd < 4; dd++) {
        t[ty][tx] = __half2float(qb[(size_t)(j0 + ty) * 384 + 256 + dd * 32 + tx]);
        __syncthreads();
        Vb[(size_t)(dd * 32 + ty) * HW + j0 + tx] = __float2half_rn(t[tx][ty] * inv);
        __syncthreads();
    }
}

// ---------------- K4: O_partial = S' @ VsT^T (tiled-S reads, split-K x8) --
// A (S) comes from contiguous 128x128 tiles: chunk kt -> tile jb=kt/4, kc=kt%4.
// mma order identical to before -> bit-identical results.
__global__ void __launch_bounds__(256, 2) k_pv()
{
    extern __shared__ __align__(16) __half dynsm[];
    __half (*As)[128][40] = reinterpret_cast<__half (*)[128][40]>(dynsm);
    __half (*Bs)[128][40] = reinterpret_cast<__half (*)[128][40]>(dynsm + NSTAGE * 128 * 40);

    const int tid = threadIdx.x;
    const int lane = tid & 31, warp = tid >> 5;
    const int wm = warp & 3, wn = warp >> 2;
    const int gid = lane >> 2, tig = lane & 3;
    const int lrow = lane & 15, lcol = (lane >> 4) << 3;
    const int r0 = tid >> 2, h8 = (tid & 3) << 3;

    const int n = blockIdx.z;
    const int ib = blockIdx.y;
    const int i0 = ib * 128;
    const int split = blockIdx.x;
    const __half* Tbase = g_S + ((size_t)(n * 32 + ib) * 32 + split * 4) * TILE_ELEMS;
    const __half* Bbase = g_VsT + (size_t)n * E_DIM * HW + split * (HW / KSPLIT);

    auto issue = [&](int kt, int buf) {
        const __half* At = Tbase + (size_t)(kt >> 2) * TILE_ELEMS + (kt & 3) * 32;
        const int k0 = kt * 32;
        cp16(&As[buf][r0][h8],      At + (size_t)r0 * 128 + h8);
        cp16(&As[buf][r0 + 64][h8], At + (size_t)(r0 + 64) * 128 + h8);
        cp16(&Bs[buf][r0][h8],      Bbase + (size_t)r0 * HW + k0 + h8);
        cp16(&Bs[buf][r0 + 64][h8], Bbase + (size_t)(r0 + 64) * HW + k0 + h8);
        cp_commit();
    };

    float c[2][8][4] = {};
    const int ktiles = (HW / KSPLIT) / 32;   // 16

    issue(0, 0);
    issue(1, 1);
    for (int kt = 0; kt < ktiles; kt++) {
        const int buf = kt % NSTAGE;
        if (kt + 2 < ktiles)        { issue(kt + 2, (kt + 2) % NSTAGE); cp_wait<2>(); }
        else if (kt + 2 == ktiles)  { cp_wait<1>(); }
        else                        { cp_wait<0>(); }
        __syncthreads();

#pragma unroll
        for (int kk = 0; kk < 2; kk++) {
            const int kb = kk << 4;
            uint32_t a[2][4];
#pragma unroll
            for (int ms = 0; ms < 2; ms++) {
                int rb = wm * 32 + ms * 16;
                ldsm_x4(a[ms][0], a[ms][1], a[ms][2], a[ms][3],
                        &As[buf][rb + lrow][kb + lcol]);
            }
            uint32_t b[8][2];
#pragma unroll
            for (int g = 0; g < 4; g++) {
                int nb = wn * 64 + g * 16;
                uint32_t m0, m1, m2, m3;
                ldsm_x4(m0, m1, m2, m3, &Bs[buf][nb + lrow][kb + lcol]);
                b[2 * g][0]     = m0; b[2 * g][1]     = m2;
                b[2 * g + 1][0] = m1; b[2 * g + 1][1] = m3;
            }
#pragma unroll
            for (int ms = 0; ms < 2; ms++)
#pragma unroll
                for (int ns = 0; ns < 8; ns++)
                    mma_f16(c[ms][ns], a[ms], b[ns]);
        }
        __syncthreads();
    }

    __half* Ob = g_Opart + ((size_t)split * N_BATCH + n) * HW * E_DIM;
#pragma unroll
    for (int ms = 0; ms < 2; ms++) {
        const int r0o = i0 + wm * 32 + ms * 16 + gid;
#pragma unroll
        for (int ns = 0; ns < 8; ns++) {
            const int col = wn * 64 + ns * 8 + 2 * tig;
            *(__half2*)(Ob + (size_t)r0o * E_DIM + col) =
                __halves2half2(__float2half_rn(c[ms][ns][0] * VS_INV),
                               __float2half_rn(c[ms][ns][1] * VS_INV));
            *(__half2*)(Ob + (size_t)(r0o + 8) * E_DIM + col) =
                __halves2half2(__float2half_rn(c[ms][ns][2] * VS_INV),
                               __float2half_rn(c[ms][ns][3] * VS_INV));
        }
    }
}

// ---------------- K5: output projection + split-K reduce ------------------
__global__ void __launch_bounds__(256, 2) k_proj(
    float* __restrict__ out, const float* __restrict__ Wout,
    const float* __restrict__ bout)
{
    __shared__ uint32_t As[128][20];
    __shared__ uint32_t Bs[128][20];
    const int n = blockIdx.z;
    const int c0 = blockIdx.y * 128;
    const int p0 = blockIdx.x * 128;
    const int tid = threadIdx.x;
    const float* Abase = Wout + (size_t)c0 * E_DIM;
    const __half* Bp0 = g_Opart + (size_t)n * HW * E_DIM + p0;
    const size_t sstr = (size_t)N_BATCH * HW * E_DIM;

    const int lane = tid & 31, warp = tid >> 5;
    const int gid = lane >> 2, tig = lane & 3;
    const int wm = warp & 3, wn = warp >> 2;
    float c[2][8][4] = {};

    for (int kt = 0; kt < E_DIM / 16; kt++) {
        const int k0 = kt * 16;
#pragma unroll
        for (int i = 0; i < 2; i++) {
            int t = tid + 256 * i;
            int row = t >> 2, c4 = (t & 3) << 2;
            float4 v = __ldg(reinterpret_cast<const float4*>(
                Abase + (size_t)row * E_DIM + k0 + c4));
            As[row][c4 + 0] = f2tf32(v.x);
            As[row][c4 + 1] = f2tf32(v.y);
            As[row][c4 + 2] = f2tf32(v.z);
            As[row][c4 + 3] = f2tf32(v.w);
        }
#pragma unroll
        for (int i = 0; i < 2; i++) {
            int t = tid + 256 * i;
            int k = t >> 5, c4 = (t & 31) << 2;
            size_t off = (size_t)(k0 + k) * HW + c4;
            float s0 = 0.f, s1 = 0.f, s2 = 0.f, s3 = 0.f;
#pragma unroll
            for (int s = 0; s < KSPLIT; s++) {
                const __half* bp = Bp0 + s * sstr + off;
                __half2 p01 = *(const __half2*)(bp);
                __half2 p23 = *(const __half2*)(bp + 2);
                s0 += __half2float(p01.x); s1 += __half2float(p01.y);
                s2 += __half2float(p23.x); s3 += __half2float(p23.y);
            }
            Bs[c4 + 0][k] = f2tf32(s0);
            Bs[c4 + 1][k] = f2tf32(s1);
            Bs[c4 + 2][k] = f2tf32(s2);
            Bs[c4 + 3][k] = f2tf32(s3);
        }
        __syncthreads();

#pragma unroll
        for (int kk = 0; kk < 2; kk++) {
            const int kb = kk << 3;
            uint32_t a[2][4];
#pragma unroll
            for (int ms = 0; ms < 2; ms++) {
                int rb = wm * 32 + ms * 16;
                a[ms][0] = As[rb + gid][kb + tig];
                a[ms][1] = As[rb + gid + 8][kb + tig];
                a[ms][2] = As[rb + gid][kb + tig + 4];
                a[ms][3] = As[rb + gid + 8][kb + tig + 4];
            }
            uint32_t b[8][2];
#pragma unroll
            for (int ns = 0; ns < 8; ns++) {
                int nb = wn * 64 + ns * 8;
                b[ns][0] = Bs[nb + gid][kb + tig];
                b[ns][1] = Bs[nb + gid][kb + tig + 4];
            }
#pragma unroll
            for (int ms = 0; ms < 2; ms++)
#pragma unroll
                for (int ns = 0; ns < 8; ns++)
                    mma_tf32(c[ms][ns], a[ms], b[ns]);
        }
        __syncthreads();
    }

    float* Yb = out + (size_t)n * C_IN * HW;
#pragma unroll
    for (int ms = 0; ms < 2; ms++) {
        const int r0 = c0 + wm * 32 + ms * 16 + gid;
        const float b0 = bout[r0], b1 = bout[r0 + 8];
#pragma unroll
        for (int ns = 0; ns < 8; ns++) {
            const int col = p0 + wn * 64 + ns * 8 + 2 * tig;
            *(float2*)(Yb + (size_t)r0 * HW + col) =
                make_float2(c[ms][ns][0] + b0, c[ms][ns][1] + b0);
            *(float2*)(Yb + (size_t)(r0 + 8) * HW + col) =
                make_float2(c[ms][ns][2] + b1, c[ms][ns][3] + b1);
        }
    }
}

// ---------------- launch ---------------------------------------------------
extern "C" void kernel_launch(void* const* d_in, const int* in_sizes, int n_in,
                              void* d_out, int out_size)
{
    (void)in_sizes; (void)n_in; (void)out_size;
    const float* x    = (const float*)d_in[0];
    const float* Wqkv = (const float*)d_in[1];
    const float* bqkv = (const float*)d_in[2];
    const float* Wout = (const float*)d_in[3];
    const float* bout = (const float*)d_in[4];
    float* out = (float*)d_out;

    // attribute sets (not allocations); applied before the pre-capture call
    cudaFuncSetAttribute(k_scores, cudaFuncAttributeMaxDynamicSharedMemorySize, SMEM_DYN);
    cudaFuncSetAttribute(k_pv,     cudaFuncAttributeMaxDynamicSharedMemorySize, SMEM_DYN);

    dim3 blk(256);
    k_qkv<<<dim3(HW / 128, OC / 128, N_BATCH), blk>>>(x, Wqkv, bqkv);
    k_scores<<<dim3(HW / 128, HW / 128, N_BATCH), blk, SMEM_DYN>>>();
    k_vscale<<<dim3(HW / 32, N_BATCH), dim3(32, 32)>>>();
    k_pv<<<dim3(KSPLIT, HW / 128, N_BATCH), blk, SMEM_DYN>>>();
    k_proj<<<dim3(HW / 128, C_IN / 128, N_BATCH), blk>>>(out, Wout, bout);
}

// round 17
// speedup vs baseline: 1.0697x; 1.0459x over previous
#include <cuda_runtime.h>
#include <cuda_fp16.h>
#include <cstdint>
#include <cstddef>

#define N_BATCH 4
#define C_IN    256
#define HW      4096
#define E_DIM   128
#define OC      384   // 3*E
#define KSPLIT  8
#define VS_SCALE 256.0f
#define VS_INV   0.00390625f

#define NSTAGE  3
#define SMEM_DYN  (2 * NSTAGE * 128 * 40 * (int)sizeof(__half))   // 61440 B
#define SMEM_PROJ ((4 * 128 * 40 + 128 * 40) * (int)sizeof(__half)) // 51200 B

// ---------------- scratch (static device globals; no runtime allocation) ----------------
__device__ __half g_qkv[(size_t)N_BATCH * OC * HW];          //  12.6 MB (n,o,p) flat, fp16
__device__ __half g_S[(size_t)N_BATCH * HW * HW];            // 134.2 MB exp(scores), fp16
__device__ float  g_colpart[(size_t)N_BATCH * 32 * HW];      //   2.1 MB per-i-block column partials
__device__ __half g_VsT[(size_t)N_BATCH * E_DIM * HW];       //   4.2 MB (n,d,j) = 256*V^T/colsum, fp16
__device__ __half g_Opart[(size_t)KSPLIT * N_BATCH * HW * E_DIM]; // 33.6 MB split-K partials, fp16

// ---------------- helpers ----------------
__device__ __forceinline__ uint32_t f2tf32(float x) {
    uint32_t r;
    asm("cvt.rna.tf32.f32 %0, %1;" : "=r"(r) : "f"(x));
    return r;
}

// fast exp for |x| <~ 2 : ~1e-7 relative error, pure FMA/ALU
__device__ __forceinline__ float fexp(float x) {
    float t = x * 1.4426950408889634f;
    int   ri = __float2int_rn(t);
    float f = t - (float)ri;
    float u = f * 0.6931471805599453f;
    float p = 1.3888889e-3f;
    p = fmaf(p, u, 8.3333333e-3f);
    p = fmaf(p, u, 4.1666667e-2f);
    p = fmaf(p, u, 1.6666667e-1f);
    p = fmaf(p, u, 0.5f);
    p = fmaf(p, u, 1.0f);
    p = fmaf(p, u, 1.0f);
    return p * __int_as_float((ri + 127) << 23);
}

__device__ __forceinline__ void mma_tf32(float c[4],
                                         const uint32_t a[4],
                                         const uint32_t b[2]) {
    asm volatile(
        "mma.sync.aligned.m16n8k8.row.col.f32.tf32.tf32.f32 "
        "{%0,%1,%2,%3}, {%4,%5,%6,%7}, {%8,%9}, {%0,%1,%2,%3};"
        : "+f"(c[0]), "+f"(c[1]), "+f"(c[2]), "+f"(c[3])
        : "r"(a[0]), "r"(a[1]), "r"(a[2]), "r"(a[3]), "r"(b[0]), "r"(b[1]));
}
__device__ __forceinline__ void mma_f16(float c[4],
                                        const uint32_t a[4],
                                        const uint32_t b[2]) {
    asm volatile(
        "mma.sync.aligned.m16n8k16.row.col.f32.f16.f16.f32 "
        "{%0,%1,%2,%3}, {%4,%5,%6,%7}, {%8,%9}, {%0,%1,%2,%3};"
        : "+f"(c[0]), "+f"(c[1]), "+f"(c[2]), "+f"(c[3])
        : "r"(a[0]), "r"(a[1]), "r"(a[2]), "r"(a[3]), "r"(b[0]), "r"(b[1]));
}

// ldmatrix x4
__device__ __forceinline__ void ldsm_x4(uint32_t& r0, uint32_t& r1,
                                        uint32_t& r2, uint32_t& r3,
                                        const void* p) {
    uint32_t addr = (uint32_t)__cvta_generic_to_shared(p);
    asm volatile("ldmatrix.sync.aligned.m8n8.x4.shared.b16 {%0,%1,%2,%3}, [%4];\n"
                 : "=r"(r0), "=r"(r1), "=r"(r2), "=r"(r3) : "r"(addr));
}

// cp.async 16B helpers
__device__ __forceinline__ void cp16(void* smem_dst, const void* gsrc) {
    uint32_t s = (uint32_t)__cvta_generic_to_shared(smem_dst);
    asm volatile("cp.async.cg.shared.global [%0], [%1], 16;\n" :: "r"(s), "l"(gsrc));
}
__device__ __forceinline__ void cp_commit() {
    asm volatile("cp.async.commit_group;\n");
}
template <int N>
__device__ __forceinline__ void cp_wait() {
    asm volatile("cp.async.wait_group %0;\n" :: "n"(N));
}

// ================= async 3-stage fp16 GEMM core (ldmatrix) ================
// C[128x128] fp32 accum, A/B fp16 [row][k] global, k-tile 32.
__device__ __forceinline__ void gemm_async_f16(
    const __half* __restrict__ Abase, int lda,
    const __half* __restrict__ Bbase, int ldb,
    int ktiles,
    __half (*As)[128][40], __half (*Bs)[128][40],
    float c[2][8][4], int tid)
{
    const int lane = tid & 31, warp = tid >> 5;
    const int wm = warp & 3, wn = warp >> 2;
    const int r0 = tid >> 2, h8 = (tid & 3) << 3;
    const int lrow = lane & 15, lcol = (lane >> 4) << 3;

    auto issue = [&](int kt, int buf) {
        const int k0 = kt * 32;
        cp16(&As[buf][r0][h8],      Abase + (size_t)r0 * lda + k0 + h8);
        cp16(&As[buf][r0 + 64][h8], Abase + (size_t)(r0 + 64) * lda + k0 + h8);
        cp16(&Bs[buf][r0][h8],      Bbase + (size_t)r0 * ldb + k0 + h8);
        cp16(&Bs[buf][r0 + 64][h8], Bbase + (size_t)(r0 + 64) * ldb + k0 + h8);
        cp_commit();
    };

    issue(0, 0);
    issue(1, 1);
    for (int kt = 0; kt < ktiles; kt++) {
        const int buf = kt % NSTAGE;
        if (kt + 2 < ktiles)        { issue(kt + 2, (kt + 2) % NSTAGE); cp_wait<2>(); }
        else if (kt + 2 == ktiles)  { cp_wait<1>(); }
        else                        { cp_wait<0>(); }
        __syncthreads();

#pragma unroll
        for (int kk = 0; kk < 2; kk++) {
            const int kb = kk << 4;
            uint32_t a[2][4];
#pragma unroll
            for (int ms = 0; ms < 2; ms++) {
                int rb = wm * 32 + ms * 16;
                ldsm_x4(a[ms][0], a[ms][1], a[ms][2], a[ms][3],
                        &As[buf][rb + lrow][kb + lcol]);
            }
            uint32_t b[8][2];
#pragma unroll
            for (int g = 0; g < 4; g++) {
                int nb = wn * 64 + g * 16;
                uint32_t m0, m1, m2, m3;
                ldsm_x4(m0, m1, m2, m3, &Bs[buf][nb + lrow][kb + lcol]);
                b[2 * g][0]     = m0; b[2 * g][1]     = m2;
                b[2 * g + 1][0] = m1; b[2 * g + 1][1] = m3;
            }
#pragma unroll
            for (int ms = 0; ms < 2; ms++)
#pragma unroll
                for (int ns = 0; ns < 8; ns++)
                    mma_f16(c[ms][ns], a[ms], b[ns]);
        }
        __syncthreads();
    }
}

// ================= LDG+cvt tf32 GEMM core (external fp32 inputs) ==========
template <bool B_KN>
__device__ __forceinline__ void gemm_main(
    const float* __restrict__ Abase, int lda,
    const float* __restrict__ Bbase, int ldb,
    int ktiles,
    uint32_t (*As)[20], uint32_t (*Bs)[20],
    float c[2][8][4], int tid)
{
    const int lane = tid & 31, warp = tid >> 5;
    const int gid = lane >> 2, tig = lane & 3;
    const int wm = warp & 3, wn = warp >> 2;

    for (int kt = 0; kt < ktiles; kt++) {
        const int k0 = kt * 16;
#pragma unroll
        for (int i = 0; i < 2; i++) {
            int t = tid + 256 * i;
            int row = t >> 2, c4 = (t & 3) << 2;
            float4 v = __ldg(reinterpret_cast<const float4*>(
                Abase + (size_t)row * lda + k0 + c4));
            As[row][c4 + 0] = f2tf32(v.x);
            As[row][c4 + 1] = f2tf32(v.y);
            As[row][c4 + 2] = f2tf32(v.z);
            As[row][c4 + 3] = f2tf32(v.w);
        }
        if (B_KN) {
#pragma unroll
            for (int i = 0; i < 2; i++) {
                int t = tid + 256 * i;
                int k = t >> 5, c4 = (t & 31) << 2;
                float4 v = __ldg(reinterpret_cast<const float4*>(
                    Bbase + (size_t)(k0 + k) * ldb + c4));
                Bs[c4 + 0][k] = f2tf32(v.x);
                Bs[c4 + 1][k] = f2tf32(v.y);
                Bs[c4 + 2][k] = f2tf32(v.z);
                Bs[c4 + 3][k] = f2tf32(v.w);
            }
        } else {
#pragma unroll
            for (int i = 0; i < 2; i++) {
                int t = tid + 256 * i;
                int row = t >> 2, c4 = (t & 3) << 2;
                float4 v = __ldg(reinterpret_cast<const float4*>(
                    Bbase + (size_t)row * ldb + k0 + c4));
                Bs[row][c4 + 0] = f2tf32(v.x);
                Bs[row][c4 + 1] = f2tf32(v.y);
                Bs[row][c4 + 2] = f2tf32(v.z);
                Bs[row][c4 + 3] = f2tf32(v.w);
            }
        }
        __syncthreads();

#pragma unroll
        for (int kk = 0; kk < 2; kk++) {
            const int kb = kk << 3;
            uint32_t a[2][4];
#pragma unroll
            for (int ms = 0; ms < 2; ms++) {
                int rb = wm * 32 + ms * 16;
                a[ms][0] = As[rb + gid][kb + tig];
                a[ms][1] = As[rb + gid + 8][kb + tig];
                a[ms][2] = As[rb + gid][kb + tig + 4];
                a[ms][3] = As[rb + gid + 8][kb + tig + 4];
            }
            uint32_t b[8][2];
#pragma unroll
            for (int ns = 0; ns < 8; ns++) {
                int nb = wn * 64 + ns * 8;
                b[ns][0] = Bs[nb + gid][kb + tig];
                b[ns][1] = Bs[nb + gid][kb + tig + 4];
            }
#pragma unroll
            for (int ms = 0; ms < 2; ms++)
#pragma unroll
                for (int ns = 0; ns < 8; ns++)
                    mma_tf32(c[ms][ns], a[ms], b[ns]);
        }
        __syncthreads();
    }
}

// ---------------- K1: QKV projection (stores fp16) ------------------------
__global__ void __launch_bounds__(256, 2) k_qkv(
    const float* __restrict__ x, const float* __restrict__ Wqkv,
    const float* __restrict__ bqkv)
{
    __shared__ uint32_t As[128][20];
    __shared__ uint32_t Bs[128][20];
    const int n = blockIdx.z;
    const int m0 = blockIdx.y * 128;
    const int p0 = blockIdx.x * 128;
    const float* Abase = Wqkv + (size_t)m0 * C_IN;               // [M][K]
    const float* Bbase = x + (size_t)n * C_IN * HW + p0;         // [K][N]
    float c[2][8][4] = {};
    gemm_main<true>(Abase, C_IN, Bbase, HW, C_IN / 16, As, Bs, c, threadIdx.x);

    const int lane = threadIdx.x & 31, warp = threadIdx.x >> 5;
    const int gid = lane >> 2, tig = lane & 3, wm = warp & 3, wn = warp >> 2;
    __half* Cb = g_qkv + (size_t)n * OC * HW;
#pragma unroll
    for (int ms = 0; ms < 2; ms++) {
        const int r0 = m0 + wm * 32 + ms * 16 + gid;
        const float b0 = bqkv[r0], b1 = bqkv[r0 + 8];
#pragma unroll
        for (int ns = 0; ns < 8; ns++) {
            const int col = p0 + wn * 64 + ns * 8 + 2 * tig;
            *(__half2*)(Cb + (size_t)r0 * HW + col) =
                __halves2half2(__float2half_rn(c[ms][ns][0] + b0),
                               __float2half_rn(c[ms][ns][1] + b0));
            *(__half2*)(Cb + (size_t)(r0 + 8) * HW + col) =
                __halves2half2(__float2half_rn(c[ms][ns][2] + b1),
                               __float2half_rn(c[ms][ns][3] + b1));
        }
    }
}

// ---------------- K2: S' = fp16(exp(Q K^T / 64)) + column partials --------
__global__ void __launch_bounds__(256, 2) k_scores()
{
    extern __shared__ __align__(16) __half dynsm[];
    __half (*As)[128][40] = reinterpret_cast<__half (*)[128][40]>(dynsm);
    __half (*Bs)[128][40] = reinterpret_cast<__half (*)[128][40]>(dynsm + NSTAGE * 128 * 40);

    const int n = blockIdx.z;
    const int i0 = blockIdx.y * 128;
    const int j0 = blockIdx.x * 128;
    const __half* qb = g_qkv + (size_t)n * OC * HW;
    float c[2][8][4] = {};
    gemm_async_f16(qb + (size_t)i0 * 384, 384, qb + (size_t)j0 * 384 + 128, 384,
                   128 / 32, As, Bs, c, threadIdx.x);

    const int tid = threadIdx.x;
    const int lane = tid & 31, warp = tid >> 5;
    const int gid = lane >> 2, tig = lane & 3, wm = warp & 3, wn = warp >> 2;
    const float scale = 0.015625f;  // 1/sqrt(4096)

    __half2* sm = reinterpret_cast<__half2*>(dynsm);          // [128][68] staging
    float* part = reinterpret_cast<float*>(sm + 128 * 68);

    float csum[8][2];
#pragma unroll
    for (int ns = 0; ns < 8; ns++) { csum[ns][0] = 0.f; csum[ns][1] = 0.f; }

#pragma unroll
    for (int ms = 0; ms < 2; ms++) {
        const int row = wm * 32 + ms * 16 + gid;
#pragma unroll
        for (int ns = 0; ns < 8; ns++) {
            const int ch2 = wn * 32 + ns * 4 + tig;
            // round exp to fp16 HERE; colsum adds the ROUNDED values so the
            // normalization matches the stored matrix exactly.
            __half h0 = __float2half_rn(fexp(c[ms][ns][0] * scale));
            __half h1 = __float2half_rn(fexp(c[ms][ns][1] * scale));
            __half h2 = __float2half_rn(fexp(c[ms][ns][2] * scale));
            __half h3 = __float2half_rn(fexp(c[ms][ns][3] * scale));
            sm[row * 68 + ch2]       = __halves2half2(h0, h1);
            sm[(row + 8) * 68 + ch2] = __halves2half2(h2, h3);
            csum[ns][0] += __half2float(h0) + __half2float(h2);
            csum[ns][1] += __half2float(h1) + __half2float(h3);
        }
    }
#pragma unroll
    for (int ns = 0; ns < 8; ns++)
#pragma unroll
        for (int jj = 0; jj < 2; jj++) {
            float v = csum[ns][jj];
            v += __shfl_xor_sync(0xffffffffu, v, 4);
            v += __shfl_xor_sync(0xffffffffu, v, 8);
            v += __shfl_xor_sync(0xffffffffu, v, 16);
            if (gid == 0)
                part[wm * 128 + wn * 64 + ns * 8 + 2 * tig + jj] = v;
        }
    __syncthreads();

    __half* Sb = g_S + (size_t)n * HW * HW;
#pragma unroll
    for (int it = 0; it < 8; it++) {
        int q = it * 256 + tid;
        int row = q >> 4, ch = q & 15;
        float4 v = *reinterpret_cast<const float4*>(sm + row * 68 + ch * 4);
        *reinterpret_cast<float4*>(Sb + (size_t)(i0 + row) * HW + j0 + ch * 8) = v;
    }
    if (tid < 128) {
        float s = part[tid] + part[128 + tid] + part[256 + tid] + part[384 + tid];
        g_colpart[((size_t)n * 32 + blockIdx.y) * HW + j0 + tid] = s;
    }
}

// ---------------- K3: colsum reduce + VsT[d][j] = fp16(256*V[j,d]/colsum[j])
__global__ void k_vscale()
{
    __shared__ float ps[32][33];
    __shared__ float t[32][33];
    const int n = blockIdx.y;
    const int j0 = blockIdx.x * 32;
    const int tx = threadIdx.x, ty = threadIdx.y;

    ps[ty][tx] = g_colpart[((size_t)n * 32 + ty) * HW + j0 + tx];
    __syncthreads();
#pragma unroll
    for (int s = 16; s > 0; s >>= 1) {
        if (ty < s) ps[ty][tx] += ps[ty + s][tx];
        __syncthreads();
    }
    const float inv = VS_SCALE / ps[0][tx];

    const __half* qb = g_qkv + (size_t)n * OC * HW;
    __half* Vb = g_VsT + (size_t)n * E_DIM * HW;
#pragma unroll
    for (int dd = 0; dd < 4; dd++) {
        t[ty][tx] = __half2float(qb[(size_t)(j0 + ty) * 384 + 256 + dd * 32 + tx]);
        __syncthreads();
        Vb[(size_t)(dd * 32 + ty) * HW + j0 + tx] = __float2half_rn(t[tx][ty] * inv);
        __syncthreads();
    }
}

// ---------------- K4: O_partial = S' @ VsT^T (fp16 MMA, split-K x8) -------
__global__ void __launch_bounds__(256, 2) k_pv()
{
    extern __shared__ __align__(16) __half dynsm[];
    __half (*As)[128][40] = reinterpret_cast<__half (*)[128][40]>(dynsm);
    __half (*Bs)[128][40] = reinterpret_cast<__half (*)[128][40]>(dynsm + NSTAGE * 128 * 40);

    const int n = blockIdx.z;
    const int i0 = blockIdx.y * 128;
    const int split = blockIdx.x;
    const int jbase = split * (HW / KSPLIT);
    const __half* Abase = g_S + (size_t)n * HW * HW + (size_t)i0 * HW + jbase;
    const __half* Bbase = g_VsT + (size_t)n * E_DIM * HW + jbase;
    float c[2][8][4] = {};
    gemm_async_f16(Abase, HW, Bbase, HW, (HW / KSPLIT) / 32, As, Bs, c, threadIdx.x);

    const int lane = threadIdx.x & 31, warp = threadIdx.x >> 5;
    const int gid = lane >> 2, tig = lane & 3, wm = warp & 3, wn = warp >> 2;
    __half* Ob = g_Opart + ((size_t)split * N_BATCH + n) * HW * E_DIM;
#pragma unroll
    for (int ms = 0; ms < 2; ms++) {
        const int r0 = i0 + wm * 32 + ms * 16 + gid;
#pragma unroll
        for (int ns = 0; ns < 8; ns++) {
            const int col = wn * 64 + ns * 8 + 2 * tig;
            *(__half2*)(Ob + (size_t)r0 * E_DIM + col) =
                __halves2half2(__float2half_rn(c[ms][ns][0] * VS_INV),
                               __float2half_rn(c[ms][ns][1] * VS_INV));
            *(__half2*)(Ob + (size_t)(r0 + 8) * E_DIM + col) =
                __halves2half2(__float2half_rn(c[ms][ns][2] * VS_INV),
                               __float2half_rn(c[ms][ns][3] * VS_INV));
        }
    }
}

// ---------------- K5: output projection (fp16 MMA) + split-K reduce -------
// y[n,c,p] = sum_e Wout[c,e] * (sum_s Opart_s)[n][e*4096 + p] + bout[c]
// A (Wout tile) staged ONCE in fp16 chunk layout; B staged per 32-k chunk.
__global__ void __launch_bounds__(256, 2) k_proj(
    float* __restrict__ out, const float* __restrict__ Wout,
    const float* __restrict__ bout)
{
    extern __shared__ __align__(16) __half dynsm[];
    __half (*Af)[128][40] = reinterpret_cast<__half (*)[128][40]>(dynsm);   // 4 chunks
    __half (*Bf)[40]      = reinterpret_cast<__half (*)[40]>(dynsm + 4 * 128 * 40);

    const int n = blockIdx.z;
    const int c0 = blockIdx.y * 128;
    const int p0 = blockIdx.x * 128;
    const int tid = threadIdx.x;
    const __half* Bp0 = g_Opart + (size_t)n * HW * E_DIM + p0;
    const size_t sstr = (size_t)N_BATCH * HW * E_DIM;

    const int lane = tid & 31, warp = tid >> 5;
    const int gid = lane >> 2, tig = lane & 3;
    const int wm = warp & 3, wn = warp >> 2;
    const int lrow = lane & 15, lcol = (lane >> 4) << 3;

    // stage A = fp16(Wout[c0..c0+127][0..127]) once, chunked [chunk][row][k32]
#pragma unroll
    for (int it = 0; it < 16; it++) {
        int q = it * 256 + tid;              // 0..4095
        int row = q >> 5;                    // 0..127
        int c4 = (q & 31) << 2;              // 0..124
        float4 v = __ldg(reinterpret_cast<const float4*>(
            Wout + (size_t)(c0 + row) * E_DIM + c4));
        int ch = c4 >> 5, off = c4 & 31;
        Af[ch][row][off + 0] = __float2half_rn(v.x);
        Af[ch][row][off + 1] = __float2half_rn(v.y);
        Af[ch][row][off + 2] = __float2half_rn(v.z);
        Af[ch][row][off + 3] = __float2half_rn(v.w);
    }

    float c[2][8][4] = {};
    const int kB = tid >> 3;                 // B staging: k row 0..31
    const int c16 = (tid & 7) << 4;          // 16 consecutive p per thread

    for (int ch = 0; ch < 4; ch++) {
        const int k0 = ch * 32;
        // sum the 8 split partials for B[k0+kB][p0+c16 .. +15], store fp16
        float acc[16];
#pragma unroll
        for (int i = 0; i < 16; i++) acc[i] = 0.f;
        const size_t off = (size_t)(k0 + kB) * HW + c16;
#pragma unroll
        for (int s = 0; s < KSPLIT; s++) {
            const __half* bp = Bp0 + s * sstr + off;
            float4 u0 = *reinterpret_cast<const float4*>(bp);
            float4 u1 = *reinterpret_cast<const float4*>(bp + 8);
            const __half2* h0 = reinterpret_cast<const __half2*>(&u0);
            const __half2* h1 = reinterpret_cast<const __half2*>(&u1);
#pragma unroll
            for (int i = 0; i < 4; i++) {
                float2 f0 = __half22float2(h0[i]);
                float2 f1 = __half22float2(h1[i]);
                acc[2 * i]     += f0.x; acc[2 * i + 1] += f0.y;
                acc[8 + 2 * i] += f1.x; acc[9 + 2 * i] += f1.y;
            }
        }
        __syncthreads();   // previous chunk's mma done before overwrite
#pragma unroll
        for (int i = 0; i < 16; i++)
            Bf[c16 + i][kB] = __float2half_rn(acc[i]);
        __syncthreads();

#pragma unroll
        for (int kk = 0; kk < 2; kk++) {
            const int kb = kk << 4;
            uint32_t a[2][4];
#pragma unroll
            for (int ms = 0; ms < 2; ms++) {
                int rb = wm * 32 + ms * 16;
                ldsm_x4(a[ms][0], a[ms][1], a[ms][2], a[ms][3],
                        &Af[ch][rb + lrow][kb + lcol]);
            }
            uint32_t b[8][2];
#pragma unroll
            for (int g = 0; g < 4; g++) {
                int nb = wn * 64 + g * 16;
                uint32_t m0, m1, m2, m3;
                ldsm_x4(m0, m1, m2, m3, &Bf[nb + lrow][kb + lcol]);
                b[2 * g][0]     = m0; b[2 * g][1]     = m2;
                b[2 * g + 1][0] = m1; b[2 * g + 1][1] = m3;
            }
#pragma unroll
            for (int ms = 0; ms < 2; ms++)
#pragma unroll
                for (int ns = 0; ns < 8; ns++)
                    mma_f16(c[ms][ns], a[ms], b[ns]);
        }
    }

    float* Yb = out + (size_t)n * C_IN * HW;
#pragma unroll
    for (int ms = 0; ms < 2; ms++) {
        const int r0 = c0 + wm * 32 + ms * 16 + gid;
        const float b0 = bout[r0], b1 = bout[r0 + 8];
#pragma unroll
        for (int ns = 0; ns < 8; ns++) {
            const int col = p0 + wn * 64 + ns * 8 + 2 * tig;
            *(float2*)(Yb + (size_t)r0 * HW + col) =
                make_float2(c[ms][ns][0] + b0, c[ms][ns][1] + b0);
            *(float2*)(Yb + (size_t)(r0 + 8) * HW + col) =
                make_float2(c[ms][ns][2] + b1, c[ms][ns][3] + b1);
        }
    }
}

// ---------------- launch ---------------------------------------------------
extern "C" void kernel_launch(void* const* d_in, const int* in_sizes, int n_in,
                              void* d_out, int out_size)
{
    (void)in_sizes; (void)n_in; (void)out_size;
    const float* x    = (const float*)d_in[0];
    const float* Wqkv = (const float*)d_in[1];
    const float* bqkv = (const float*)d_in[2];
    const float* Wout = (const float*)d_in[3];
    const float* bout = (const float*)d_in[4];
    float* out = (float*)d_out;

    // attribute sets (not allocations); applied before the pre-capture call
    cudaFuncSetAttribute(k_scores, cudaFuncAttributeMaxDynamicSharedMemorySize, SMEM_DYN);
    cudaFuncSetAttribute(k_pv,     cudaFuncAttributeMaxDynamicSharedMemorySize, SMEM_DYN);
    cudaFuncSetAttribute(k_proj,   cudaFuncAttributeMaxDynamicSharedMemorySize, SMEM_PROJ);

    dim3 blk(256);
    k_qkv<<<dim3(HW / 128, OC / 128, N_BATCH), blk>>>(x, Wqkv, bqkv);
    k_scores<<<dim3(HW / 128, HW / 128, N_BATCH), blk, SMEM_DYN>>>();
    k_vscale<<<dim3(HW / 32, N_BATCH), dim3(32, 32)>>>();
    k_pv<<<dim3(KSPLIT, HW / 128, N_BATCH), blk, SMEM_DYN>>>();
    k_proj<<<dim3(HW / 128, C_IN / 128, N_BATCH), blk, SMEM_PROJ>>>(out, Wout, bout);
}